// round 1
// baseline (speedup 1.0000x reference)
#include <cuda_runtime.h>
#include <math.h>

// Problem constants
#define BB    32
#define NQ    197
#define NV    1568
#define DIMD  768
#define HH    12
#define DD    64
#define FF    8
#define NKC   196     // keys per fine chunk = NV/FF, also NQ-1 queries
#define NOUT  1569    // 1 + FF*NKC
#define BHN   384     // BB*HH

// ---------------- scratch (device globals; no allocation allowed) ----------
__device__ float g_q[(size_t)BHN * NQ * DD];      // scaled q, heads layout [bh][nq][d]
__device__ float g_k[(size_t)BHN * NV * DD];      // [bh][nv][d]
__device__ float g_v[(size_t)BHN * NV * DD];      // [bh][nv][d]
__device__ float g_att[(size_t)BHN * NOUT * DD];  // [bh][1+f*196+q][d], row 0 = cls

// ---------------------------------------------------------------------------
// Tiled SGEMM: C = A(MxK) @ B(KxN), BM=BN=128, BK=16, 256 threads, 8x8/thread.
// MODE 0: A=question, write q heads-layout * 0.125
// MODE 1: A=x,        write k/v heads-layout (N=1536 split)
// MODE 2: A=gather(g_att heads layout), +bias, write d_out row-major
// ---------------------------------------------------------------------------
template<int MODE>
__global__ __launch_bounds__(256)
void gemm128(const float* __restrict__ A, const float* __restrict__ Bm,
             const float* __restrict__ bias, float* __restrict__ Cout,
             int M, int N, int K)
{
    __shared__ float As[16][128];   // transposed A tile: As[k][m]
    __shared__ float Bs[16][128];   // Bs[k][n]

    const int row0 = blockIdx.y * 128;
    const int col0 = blockIdx.x * 128;
    const int tid  = threadIdx.x;
    const int tx   = tid & 15;
    const int ty   = tid >> 4;

    float acc[8][8];
#pragma unroll
    for (int i = 0; i < 8; i++)
#pragma unroll
        for (int j = 0; j < 8; j++) acc[i][j] = 0.f;

    for (int k0 = 0; k0 < K; k0 += 16) {
        // ---- load A tile (128x16), transposed into As
#pragma unroll
        for (int half = 0; half < 2; half++) {
            int r    = (tid >> 2) + half * 64;
            int c4   = (tid & 3) * 4;
            int grow = row0 + r;
            float4 av = make_float4(0.f, 0.f, 0.f, 0.f);
            if (grow < M) {
                if (MODE == 2) {
                    int b_ = grow / NOUT;
                    int n_ = grow - b_ * NOUT;
                    int kk = k0 + c4;
                    int h  = kk >> 6;
                    int dd = kk & 63;
                    av = *(const float4*)&g_att[(((size_t)(b_ * HH + h) * NOUT + n_) << 6) + dd];
                } else {
                    av = *(const float4*)&A[(size_t)grow * K + k0 + c4];
                }
            }
            As[c4 + 0][r] = av.x;
            As[c4 + 1][r] = av.y;
            As[c4 + 2][r] = av.z;
            As[c4 + 3][r] = av.w;
        }
        // ---- load B tile (16x128)
#pragma unroll
        for (int half = 0; half < 2; half++) {
            int rr = (tid >> 5) + half * 8;
            int cc = (tid & 31) * 4;
            *(float4*)&Bs[rr][cc] = *(const float4*)&Bm[(size_t)(k0 + rr) * N + col0 + cc];
        }
        __syncthreads();

#pragma unroll
        for (int kk = 0; kk < 16; kk++) {
            float a[8], b[8];
            *(float4*)&a[0] = *(float4*)&As[kk][ty * 8];
            *(float4*)&a[4] = *(float4*)&As[kk][ty * 8 + 4];
            *(float4*)&b[0] = *(float4*)&Bs[kk][tx * 8];
            *(float4*)&b[4] = *(float4*)&Bs[kk][tx * 8 + 4];
#pragma unroll
            for (int i = 0; i < 8; i++)
#pragma unroll
                for (int j = 0; j < 8; j++)
                    acc[i][j] = fmaf(a[i], b[j], acc[i][j]);
        }
        __syncthreads();
    }

    // ---- epilogue
#pragma unroll
    for (int i = 0; i < 8; i++) {
        int row = row0 + ty * 8 + i;
        if (row >= M) continue;

        if (MODE == 0) {
            int b_ = row / NQ;
            int nq = row - b_ * NQ;
#pragma unroll
            for (int j4 = 0; j4 < 8; j4 += 4) {
                int col = col0 + tx * 8 + j4;
                int h = col >> 6, dd = col & 63;
                float4 v = make_float4(acc[i][j4] * 0.125f, acc[i][j4 + 1] * 0.125f,
                                       acc[i][j4 + 2] * 0.125f, acc[i][j4 + 3] * 0.125f);
                *(float4*)&g_q[(((size_t)(b_ * HH + h) * NQ + nq) << 6) + dd] = v;
            }
        } else if (MODE == 1) {
            int b_ = row / NV;
            int nv = row - b_ * NV;
#pragma unroll
            for (int j4 = 0; j4 < 8; j4 += 4) {
                int col = col0 + tx * 8 + j4;
                float4 v = make_float4(acc[i][j4], acc[i][j4 + 1], acc[i][j4 + 2], acc[i][j4 + 3]);
                if (col < DIMD) {
                    int h = col >> 6, dd = col & 63;
                    *(float4*)&g_k[(((size_t)(b_ * HH + h) * NV + nv) << 6) + dd] = v;
                } else {
                    int c2 = col - DIMD;
                    int h = c2 >> 6, dd = c2 & 63;
                    *(float4*)&g_v[(((size_t)(b_ * HH + h) * NV + nv) << 6) + dd] = v;
                }
            }
        } else {  // MODE 2
#pragma unroll
            for (int j4 = 0; j4 < 8; j4 += 4) {
                int col = col0 + tx * 8 + j4;
                float4 bi = *(const float4*)&bias[col];
                float4 v = make_float4(acc[i][j4] + bi.x, acc[i][j4 + 1] + bi.y,
                                       acc[i][j4 + 2] + bi.z, acc[i][j4 + 3] + bi.w);
                *(float4*)&Cout[(size_t)row * DIMD + col] = v;
            }
        }
    }
}

// ---------------------------------------------------------------------------
// cls-token attention: per bh, 1 query vs 1568 keys. One block / bh.
// ---------------------------------------------------------------------------
__global__ __launch_bounds__(256)
void cls_attn()
{
    __shared__ float qsh[64];
    __shared__ float ssh[NV];
    __shared__ float red[40];
    __shared__ float osh[4][64];

    const int bh   = blockIdx.x;
    const int tid  = threadIdx.x;
    const int lane = tid & 31;
    const int warp = tid >> 5;

    if (tid < 64) qsh[tid] = g_q[((size_t)bh * NQ) * 64 + tid];
    __syncthreads();

    // scores: one warp per key (round-robin)
    for (int j = warp; j < NV; j += 8) {
        const float* kr = &g_k[((size_t)bh * NV + j) * 64];
        float p = qsh[lane] * kr[lane] + qsh[lane + 32] * kr[lane + 32];
#pragma unroll
        for (int o = 16; o > 0; o >>= 1) p += __shfl_xor_sync(0xffffffffu, p, o);
        if (lane == 0) ssh[j] = p;
    }
    __syncthreads();

    // block max
    float m = -1e30f;
    for (int j = tid; j < NV; j += 256) m = fmaxf(m, ssh[j]);
#pragma unroll
    for (int o = 16; o > 0; o >>= 1) m = fmaxf(m, __shfl_xor_sync(0xffffffffu, m, o));
    if (lane == 0) red[warp] = m;
    __syncthreads();
    if (tid == 0) {
        float mm = red[0];
        for (int w = 1; w < 8; w++) mm = fmaxf(mm, red[w]);
        red[32] = mm;
    }
    __syncthreads();
    m = red[32];

    // exp + sum
    float s = 0.f;
    for (int j = tid; j < NV; j += 256) {
        float e = __expf(ssh[j] - m);
        ssh[j] = e;
        s += e;
    }
#pragma unroll
    for (int o = 16; o > 0; o >>= 1) s += __shfl_xor_sync(0xffffffffu, s, o);
    if (lane == 0) red[8 + warp] = s;
    __syncthreads();
    if (tid == 0) {
        float ss = 0.f;
        for (int w = 0; w < 8; w++) ss += red[8 + w];
        red[33] = 1.f / ss;
    }
    __syncthreads();
    const float inv = red[33];

    // output: 4 partial groups x 64 dims (coalesced v reads)
    const int g = tid >> 6, dd = tid & 63;
    float o = 0.f;
    for (int j = g; j < NV; j += 4)
        o = fmaf(ssh[j], g_v[((size_t)bh * NV + j) * 64 + dd], o);
    osh[g][dd] = o;
    __syncthreads();
    if (tid < 64) {
        float r = (osh[0][tid] + osh[1][tid] + osh[2][tid] + osh[3][tid]) * inv;
        g_att[((size_t)bh * NOUT) * 64 + tid] = r;
    }
}

// ---------------------------------------------------------------------------
// Fine attention: one block per (bh, f): 196 queries vs 196 keys, d=64.
// K/V resident in smem; queries processed in chunks of 64 with register-tiled
// S (4x13/thread) and O (4x4/thread) phases, conflict-free smem layouts.
// ---------------------------------------------------------------------------
constexpr int QT_S = 68;    // Qt[64][68] transposed q chunk
constexpr int KS_S = 68;    // Ks[196][68]
constexpr int S_S  = 197;   // Ssc[64][197]
constexpr int FINE_SMEM = (64 * QT_S + NKC * KS_S + NKC * 64 + 64 * S_S) * 4;  // 171,328 B

__global__ __launch_bounds__(256)
void fine_attn()
{
    extern __shared__ float sm[];
    float* Qt  = sm;
    float* Ks  = Qt + 64 * QT_S;
    float* Vs  = Ks + NKC * KS_S;
    float* Ssc = Vs + NKC * 64;

    const int blk  = blockIdx.x;
    const int bh   = blk >> 3;
    const int f    = blk & 7;
    const int tid  = threadIdx.x;
    const int tx   = tid & 15;
    const int ty   = tid >> 4;
    const int lane = tid & 31;
    const int warp = tid >> 5;

    // load K, V tiles (float4, coalesced)
    const float* kg = &g_k[((size_t)bh * NV + f * NKC) * 64];
    const float* vg = &g_v[((size_t)bh * NV + f * NKC) * 64];
    for (int idx = tid; idx < NKC * 16; idx += 256) {
        int j = idx >> 4, d4 = (idx & 15) << 2;
        float4 kv = *(const float4*)&kg[j * 64 + d4];
        *(float4*)&Ks[j * KS_S + d4] = kv;
        float4 vv = *(const float4*)&vg[j * 64 + d4];
        *(float4*)&Vs[j * 64 + d4] = vv;
    }

    for (int qc = 0; qc < 4; qc++) {
        int rows = NKC - qc * 64;
        if (rows > 64) rows = 64;

        // fill Qt transposed (zero-pad invalid rows)
        for (int idx = tid; idx < 64 * 64; idx += 256) {
            int i = idx >> 6, d = idx & 63;
            float v = 0.f;
            if (i < rows)
                v = g_q[((size_t)bh * NQ + 1 + qc * 64 + i) * 64 + d];
            Qt[d * QT_S + i] = v;
        }
        __syncthreads();  // (covers K/V load on first iteration)

        // ---- S = Qc @ K^T : query i = tx+16*ii, key j = ty+16*c
        float acc[4][13];
#pragma unroll
        for (int ii = 0; ii < 4; ii++)
#pragma unroll
            for (int c = 0; c < 13; c++) acc[ii][c] = 0.f;
        const int cc = (ty < 4) ? 13 : 12;

        for (int d = 0; d < 64; d++) {
            float q0 = Qt[d * QT_S + tx];
            float q1 = Qt[d * QT_S + tx + 16];
            float q2 = Qt[d * QT_S + tx + 32];
            float q3 = Qt[d * QT_S + tx + 48];
#pragma unroll
            for (int c = 0; c < 13; c++) {
                if (c < cc) {
                    float kv = Ks[(ty + 16 * c) * KS_S + d];
                    acc[0][c] = fmaf(q0, kv, acc[0][c]);
                    acc[1][c] = fmaf(q1, kv, acc[1][c]);
                    acc[2][c] = fmaf(q2, kv, acc[2][c]);
                    acc[3][c] = fmaf(q3, kv, acc[3][c]);
                }
            }
        }
#pragma unroll
        for (int c = 0; c < 13; c++) {
            if (c < cc) {
                int j = ty + 16 * c;
#pragma unroll
                for (int ii = 0; ii < 4; ii++)
                    Ssc[(tx + 16 * ii) * S_S + j] = acc[ii][c];
            }
        }
        __syncthreads();

        // ---- softmax (warp per 8 rows)
        for (int r = warp * 8; r < warp * 8 + 8; r++) {
            float* srow = &Ssc[r * S_S];
            float mx = -1e30f;
            for (int j = lane; j < NKC; j += 32) mx = fmaxf(mx, srow[j]);
#pragma unroll
            for (int o = 16; o > 0; o >>= 1) mx = fmaxf(mx, __shfl_xor_sync(0xffffffffu, mx, o));
            float sum = 0.f;
            for (int j = lane; j < NKC; j += 32) {
                float e = __expf(srow[j] - mx);
                srow[j] = e;
                sum += e;
            }
#pragma unroll
            for (int o = 16; o > 0; o >>= 1) sum += __shfl_xor_sync(0xffffffffu, sum, o);
            float inv = 1.f / sum;
            for (int j = lane; j < NKC; j += 32) srow[j] *= inv;
        }
        __syncthreads();

        // ---- O = P @ V : row i = ty*4+ii, dim dd = tx*4+jj
        float o4[4][4];
#pragma unroll
        for (int ii = 0; ii < 4; ii++)
#pragma unroll
            for (int jj = 0; jj < 4; jj++) o4[ii][jj] = 0.f;

        for (int k = 0; k < NKC; k++) {
            float4 vv = *(float4*)&Vs[k * 64 + tx * 4];
#pragma unroll
            for (int ii = 0; ii < 4; ii++) {
                float sv = Ssc[(ty * 4 + ii) * S_S + k];
                o4[ii][0] = fmaf(sv, vv.x, o4[ii][0]);
                o4[ii][1] = fmaf(sv, vv.y, o4[ii][1]);
                o4[ii][2] = fmaf(sv, vv.z, o4[ii][2]);
                o4[ii][3] = fmaf(sv, vv.w, o4[ii][3]);
            }
        }
#pragma unroll
        for (int ii = 0; ii < 4; ii++) {
            int qrow = qc * 64 + ty * 4 + ii;
            if (qrow < NKC) {
                int n = 1 + f * NKC + qrow;
                float4 ov = make_float4(o4[ii][0], o4[ii][1], o4[ii][2], o4[ii][3]);
                *(float4*)&g_att[((size_t)bh * NOUT + n) * 64 + tx * 4] = ov;
            }
        }
        __syncthreads();
    }
}

// ---------------------------------------------------------------------------
extern "C" void kernel_launch(void* const* d_in, const int* in_sizes, int n_in,
                              void* d_out, int out_size)
{
    const float* x        = (const float*)d_in[0];
    const float* question = (const float*)d_in[1];
    const float* Wq       = (const float*)d_in[2];
    const float* Wkv      = (const float*)d_in[3];
    const float* Wproj    = (const float*)d_in[4];
    const float* bproj    = (const float*)d_in[5];
    float* out = (float*)d_out;

    cudaFuncSetAttribute(fine_attn, cudaFuncAttributeMaxDynamicSharedMemorySize, FINE_SMEM);

    // q projection (scaled, heads layout)
    gemm128<0><<<dim3(DIMD / 128, (BB * NQ + 127) / 128), 256>>>(
        question, Wq, nullptr, nullptr, BB * NQ, DIMD, DIMD);

    // kv projection (split into k/v heads layout)
    gemm128<1><<<dim3((2 * DIMD) / 128, (BB * NV) / 128), 256>>>(
        x, Wkv, nullptr, nullptr, BB * NV, 2 * DIMD, DIMD);

    // attention
    cls_attn<<<BHN, 256>>>();
    fine_attn<<<BHN * FF, 256, FINE_SMEM>>>();

    // output projection + bias
    gemm128<2><<<dim3(DIMD / 128, (BB * NOUT + 127) / 128), 256>>>(
        nullptr, Wproj, bproj, out, BB * NOUT, DIMD, DIMD);
}

// round 3
// speedup vs baseline: 1.8365x; 1.8365x over previous
#include <cuda_runtime.h>
#include <cstdint>
#include <math.h>

// Problem constants
#define BB    32
#define NQ    197
#define NV    1568
#define DIMD  768
#define HH    12
#define FF    8
#define NKC   196
#define NOUT  1569
#define BHN   384
#define KDIM  768

// ---------------- scratch (device globals) ----------------
__device__ float g_q[(size_t)BHN * NQ * 64];
__device__ float g_k[(size_t)BHN * NV * 64];
__device__ float g_v[(size_t)BHN * NV * 64];
__device__ float g_att[(size_t)BHN * NOUT * 64];
__device__ float g_wqT[768 * 768];      // Wq^T   [N][K], tf32-rounded
__device__ float g_wkvT[1536 * 768];    // Wkv^T  [N][K], tf32-rounded
__device__ float g_wpT[768 * 768];      // Wproj^T[N][K], tf32-rounded

// ======================= helpers =======================
__device__ __forceinline__ uint32_t smem_to_u32(const void* p) {
    uint32_t a;
    asm("{ .reg .u64 t; cvta.to.shared.u64 t, %1; cvt.u32.u64 %0, t; }" : "=r"(a) : "l"(p));
    return a;
}
__device__ __forceinline__ uint32_t to_tf32_rn(float x) {
    uint32_t r;
    asm("cvt.rn.tf32.f32 %0, %1;" : "=r"(r) : "f"(x));
    return r;
}
__device__ __forceinline__ void cp_async16(uint32_t smem_addr, const void* gptr, bool pred) {
    int sz = pred ? 16 : 0;
    asm volatile("cp.async.cg.shared.global [%0], [%1], 16, %2;"
                 :: "r"(smem_addr), "l"(gptr), "r"(sz));
}
#define CP_COMMIT() asm volatile("cp.async.commit_group;" ::: "memory")
#define CP_WAIT(n)  asm volatile("cp.async.wait_group %0;" :: "n"(n) : "memory")

__device__ __forceinline__ void mma_tf32(float* c, const uint32_t* a, const uint32_t* b) {
    asm volatile(
        "mma.sync.aligned.m16n8k8.row.col.f32.tf32.tf32.f32 "
        "{%0,%1,%2,%3}, {%4,%5,%6,%7}, {%8,%9}, {%0,%1,%2,%3};"
        : "+f"(c[0]), "+f"(c[1]), "+f"(c[2]), "+f"(c[3])
        : "r"(a[0]), "r"(a[1]), "r"(a[2]), "r"(a[3]), "r"(b[0]), "r"(b[1]));
}

// ======================= weight transpose + tf32 round =======================
// src: [K, N] row-major -> dst: [N, K] row-major, values rounded to tf32 (RN).
__global__ __launch_bounds__(256)
void transposeW(const float* __restrict__ src, int which, int K, int N)
{
    float* dst = (which == 0) ? g_wqT : (which == 1) ? g_wkvT : g_wpT;
    __shared__ float t[32][33];
    int bx = blockIdx.x * 32;   // N block
    int by = blockIdx.y * 32;   // K block
    int txl = threadIdx.x & 31;
    int tyl = threadIdx.x >> 5;
#pragma unroll
    for (int j = 0; j < 32; j += 8)
        t[tyl + j][txl] = src[(size_t)(by + tyl + j) * N + bx + txl];
    __syncthreads();
#pragma unroll
    for (int j = 0; j < 32; j += 8)
        dst[(size_t)(bx + tyl + j) * K + by + txl] =
            __uint_as_float(to_tf32_rn(t[txl][tyl + j]));
}

// ======================= mma.sync tf32 GEMM =======================
// C(M x N) = A(M x 768) @ W(768 x N), W supplied transposed+rounded [N][768].
// 128x128x32 tiles, 256 threads (8 warps 4Mx2N), warp does 32x64 via m16n8k8.
// MODE 0: A=question -> g_q heads layout * 0.125
// MODE 1: A=x        -> g_k / g_v heads layout
// MODE 2: A=gather(g_att heads layout) -> d_out + bias
constexpr int BM = 128, BN = 128, BK = 32;
constexpr int SK = 36;                                   // padded row stride (words)
constexpr int A_BYTES = BM * SK * 4;                     // 18432
constexpr int STAGE_BYTES = 2 * A_BYTES;                 // 36864 (A then B)
constexpr int GEMM_SMEM = 2 * STAGE_BYTES;               // 73728
constexpr int KT = KDIM / BK;                            // 24

template<int MODE>
__global__ __launch_bounds__(256, 2)
void gemm_tc(const float* __restrict__ A, const float* __restrict__ bias,
             float* __restrict__ Cout, int M)
{
    extern __shared__ char sm[];
    const uint32_t sbase = smem_to_u32(sm);
    const int tid   = threadIdx.x;
    const int warp  = tid >> 5;
    const int lane  = tid & 31;
    const int group = lane >> 2;     // 0..7
    const int tig   = lane & 3;      // 0..3
    const int wm    = warp & 3;      // 0..3  -> M offset wm*32
    const int wn    = warp >> 2;     // 0..1  -> N offset wn*64
    const int row0  = blockIdx.y * BM;
    const int col0  = blockIdx.x * BN;

    const float* BT = (MODE == 0) ? g_wqT : (MODE == 1) ? g_wkvT : g_wpT;

    float acc[2][8][4];
#pragma unroll
    for (int mt = 0; mt < 2; mt++)
#pragma unroll
        for (int nt = 0; nt < 8; nt++)
#pragma unroll
            for (int c = 0; c < 4; c++) acc[mt][nt][c] = 0.f;

    // per-thread load coordinates (element idx = tid + it*256; 8 float4 per row)
    const int lr = tid >> 3;           // base row 0..31 (stride 32 over its)
    const int lk4 = (tid & 7) << 2;    // k offset 0,4,...,28

    auto load_stage = [&](int kt, int s) {
        const uint32_t aoff = sbase + s * STAGE_BYTES;
        const uint32_t boff = aoff + A_BYTES;
        const int k0 = kt * BK;
#pragma unroll
        for (int it = 0; it < 4; it++) {
            int r = lr + it * 32;
            int grow = row0 + r;
            bool ok = grow < M;
            int gr = ok ? grow : 0;
            const float* src;
            if (MODE == 2) {
                int b_ = gr / NOUT;
                int n_ = gr - b_ * NOUT;
                int kk = k0 + lk4;
                int h = kk >> 6, dd = kk & 63;
                src = &g_att[(((size_t)(b_ * HH + h) * NOUT + n_) << 6) + dd];
            } else {
                src = &A[(size_t)gr * KDIM + k0 + lk4];
            }
            cp_async16(aoff + (uint32_t)(r * SK + lk4) * 4, src, ok);
        }
#pragma unroll
        for (int it = 0; it < 4; it++) {
            int r = lr + it * 32;
            cp_async16(boff + (uint32_t)(r * SK + lk4) * 4,
                       &BT[(size_t)(col0 + r) * KDIM + k0 + lk4], true);
        }
        CP_COMMIT();
    };

    load_stage(0, 0);

    for (int kt = 0; kt < KT; kt++) {
        const int cur = kt & 1;
        if (kt + 1 < KT) {
            load_stage(kt + 1, (kt + 1) & 1);
            CP_WAIT(1);
        } else {
            CP_WAIT(0);
        }
        __syncthreads();

        const float* As = (const float*)(sm + cur * STAGE_BYTES);
        const float* Bs = (const float*)(sm + cur * STAGE_BYTES + A_BYTES);

#pragma unroll
        for (int ks = 0; ks < 4; ks++) {
            const int kc = ks * 8 + tig;
            uint32_t af[2][4];
#pragma unroll
            for (int mt = 0; mt < 2; mt++) {
                int r = wm * 32 + mt * 16 + group;
                af[mt][0] = to_tf32_rn(As[r * SK + kc]);
                af[mt][1] = to_tf32_rn(As[(r + 8) * SK + kc]);
                af[mt][2] = to_tf32_rn(As[r * SK + kc + 4]);
                af[mt][3] = to_tf32_rn(As[(r + 8) * SK + kc + 4]);
            }
#pragma unroll
            for (int nt = 0; nt < 8; nt++) {
                int n = wn * 64 + nt * 8 + group;
                uint32_t bf[2];
                bf[0] = __float_as_uint(Bs[n * SK + kc]);
                bf[1] = __float_as_uint(Bs[n * SK + kc + 4]);
                mma_tf32(acc[0][nt], af[0], bf);
                mma_tf32(acc[1][nt], af[1], bf);
            }
        }
        __syncthreads();
    }

    // ---- epilogue: scatter per MODE (c0,c1 = row, cols 2tig..; c2,c3 = row+8)
#pragma unroll
    for (int mt = 0; mt < 2; mt++) {
#pragma unroll
        for (int half = 0; half < 2; half++) {
            int row = row0 + wm * 32 + mt * 16 + group + half * 8;
            if (row >= M) continue;
            // precompute row decomposition
            int b_, n_;
            if (MODE == 0) { b_ = row / NQ;   n_ = row - b_ * NQ; }
            else if (MODE == 1) { b_ = row / NV; n_ = row - b_ * NV; }
            else { b_ = 0; n_ = 0; }
#pragma unroll
            for (int nt = 0; nt < 8; nt++) {
                int col = col0 + wn * 64 + nt * 8 + tig * 2;
                float v0 = acc[mt][nt][half * 2 + 0];
                float v1 = acc[mt][nt][half * 2 + 1];
                if (MODE == 0) {
                    int h = col >> 6, dd = col & 63;
                    float2 w = make_float2(v0 * 0.125f, v1 * 0.125f);
                    *(float2*)&g_q[(((size_t)(b_ * HH + h) * NQ + n_) << 6) + dd] = w;
                } else if (MODE == 1) {
                    float2 w = make_float2(v0, v1);
                    if (col < DIMD) {
                        int h = col >> 6, dd = col & 63;
                        *(float2*)&g_k[(((size_t)(b_ * HH + h) * NV + n_) << 6) + dd] = w;
                    } else {
                        int c2 = col - DIMD;
                        int h = c2 >> 6, dd = c2 & 63;
                        *(float2*)&g_v[(((size_t)(b_ * HH + h) * NV + n_) << 6) + dd] = w;
                    }
                } else {
                    float2 w = make_float2(v0 + bias[col], v1 + bias[col + 1]);
                    *(float2*)&Cout[(size_t)row * DIMD + col] = w;
                }
            }
        }
    }
}

// ======================= cls-token attention =======================
__global__ __launch_bounds__(256)
void cls_attn()
{
    __shared__ float qsh[64];
    __shared__ float ssh[NV];
    __shared__ float red[40];
    __shared__ float osh[4][64];

    const int bh   = blockIdx.x;
    const int tid  = threadIdx.x;
    const int lane = tid & 31;
    const int warp = tid >> 5;

    if (tid < 64) qsh[tid] = g_q[((size_t)bh * NQ) * 64 + tid];
    __syncthreads();

    for (int j = warp; j < NV; j += 8) {
        const float* kr = &g_k[((size_t)bh * NV + j) * 64];
        float p = qsh[lane] * kr[lane] + qsh[lane + 32] * kr[lane + 32];
#pragma unroll
        for (int o = 16; o > 0; o >>= 1) p += __shfl_xor_sync(0xffffffffu, p, o);
        if (lane == 0) ssh[j] = p;
    }
    __syncthreads();

    float m = -1e30f;
    for (int j = tid; j < NV; j += 256) m = fmaxf(m, ssh[j]);
#pragma unroll
    for (int o = 16; o > 0; o >>= 1) m = fmaxf(m, __shfl_xor_sync(0xffffffffu, m, o));
    if (lane == 0) red[warp] = m;
    __syncthreads();
    if (tid == 0) {
        float mm = red[0];
        for (int w = 1; w < 8; w++) mm = fmaxf(mm, red[w]);
        red[32] = mm;
    }
    __syncthreads();
    m = red[32];

    float s = 0.f;
    for (int j = tid; j < NV; j += 256) {
        float e = __expf(ssh[j] - m);
        ssh[j] = e;
        s += e;
    }
#pragma unroll
    for (int o = 16; o > 0; o >>= 1) s += __shfl_xor_sync(0xffffffffu, s, o);
    if (lane == 0) red[8 + warp] = s;
    __syncthreads();
    if (tid == 0) {
        float ss = 0.f;
        for (int w = 0; w < 8; w++) ss += red[8 + w];
        red[33] = 1.f / ss;
    }
    __syncthreads();
    const float inv = red[33];

    const int g = tid >> 6, dd = tid & 63;
    float o = 0.f;
    for (int j = g; j < NV; j += 4)
        o = fmaf(ssh[j], g_v[((size_t)bh * NV + j) * 64 + dd], o);
    osh[g][dd] = o;
    __syncthreads();
    if (tid < 64) {
        float r = (osh[0][tid] + osh[1][tid] + osh[2][tid] + osh[3][tid]) * inv;
        g_att[((size_t)bh * NOUT) * 64 + tid] = r;
    }
}

// ======================= fine attention =======================
constexpr int QT_S = 68;
constexpr int KS_S = 68;
constexpr int S_S  = 197;
constexpr int FINE_SMEM = (64 * QT_S + NKC * KS_S + NKC * 64 + 64 * S_S) * 4;

__global__ __launch_bounds__(256)
void fine_attn()
{
    extern __shared__ float smf[];
    float* Qt  = smf;
    float* Ks  = Qt + 64 * QT_S;
    float* Vs  = Ks + NKC * KS_S;
    float* Ssc = Vs + NKC * 64;

    const int blk  = blockIdx.x;
    const int bh   = blk >> 3;
    const int f    = blk & 7;
    const int tid  = threadIdx.x;
    const int tx   = tid & 15;
    const int ty   = tid >> 4;
    const int lane = tid & 31;
    const int warp = tid >> 5;

    const float* kg = &g_k[((size_t)bh * NV + f * NKC) * 64];
    const float* vg = &g_v[((size_t)bh * NV + f * NKC) * 64];
    for (int idx = tid; idx < NKC * 16; idx += 256) {
        int j = idx >> 4, d4 = (idx & 15) << 2;
        float4 kv = *(const float4*)&kg[j * 64 + d4];
        *(float4*)&Ks[j * KS_S + d4] = kv;
        float4 vv = *(const float4*)&vg[j * 64 + d4];
        *(float4*)&Vs[j * 64 + d4] = vv;
    }

    for (int qc = 0; qc < 4; qc++) {
        int rows = NKC - qc * 64;
        if (rows > 64) rows = 64;

        for (int idx = tid; idx < 64 * 64; idx += 256) {
            int i = idx >> 6, d = idx & 63;
            float v = 0.f;
            if (i < rows)
                v = g_q[((size_t)bh * NQ + 1 + qc * 64 + i) * 64 + d];
            Qt[d * QT_S + i] = v;
        }
        __syncthreads();

        float acc[4][13];
#pragma unroll
        for (int ii = 0; ii < 4; ii++)
#pragma unroll
            for (int c = 0; c < 13; c++) acc[ii][c] = 0.f;
        const int cc = (ty < 4) ? 13 : 12;

        for (int d = 0; d < 64; d++) {
            float q0 = Qt[d * QT_S + tx];
            float q1 = Qt[d * QT_S + tx + 16];
            float q2 = Qt[d * QT_S + tx + 32];
            float q3 = Qt[d * QT_S + tx + 48];
#pragma unroll
            for (int c = 0; c < 13; c++) {
                if (c < cc) {
                    float kv = Ks[(ty + 16 * c) * KS_S + d];
                    acc[0][c] = fmaf(q0, kv, acc[0][c]);
                    acc[1][c] = fmaf(q1, kv, acc[1][c]);
                    acc[2][c] = fmaf(q2, kv, acc[2][c]);
                    acc[3][c] = fmaf(q3, kv, acc[3][c]);
                }
            }
        }
#pragma unroll
        for (int c = 0; c < 13; c++) {
            if (c < cc) {
                int j = ty + 16 * c;
#pragma unroll
                for (int ii = 0; ii < 4; ii++)
                    Ssc[(tx + 16 * ii) * S_S + j] = acc[ii][c];
            }
        }
        __syncthreads();

        for (int r = warp * 8; r < warp * 8 + 8; r++) {
            float* srow = &Ssc[r * S_S];
            float mx = -1e30f;
            for (int j = lane; j < NKC; j += 32) mx = fmaxf(mx, srow[j]);
#pragma unroll
            for (int o = 16; o > 0; o >>= 1) mx = fmaxf(mx, __shfl_xor_sync(0xffffffffu, mx, o));
            float sum = 0.f;
            for (int j = lane; j < NKC; j += 32) {
                float e = __expf(srow[j] - mx);
                srow[j] = e;
                sum += e;
            }
#pragma unroll
            for (int o = 16; o > 0; o >>= 1) sum += __shfl_xor_sync(0xffffffffu, sum, o);
            float inv = 1.f / sum;
            for (int j = lane; j < NKC; j += 32) srow[j] *= inv;
        }
        __syncthreads();

        float o4[4][4];
#pragma unroll
        for (int ii = 0; ii < 4; ii++)
#pragma unroll
            for (int jj = 0; jj < 4; jj++) o4[ii][jj] = 0.f;

        for (int k = 0; k < NKC; k++) {
            float4 vv = *(float4*)&Vs[k * 64 + tx * 4];
#pragma unroll
            for (int ii = 0; ii < 4; ii++) {
                float sv = Ssc[(ty * 4 + ii) * S_S + k];
                o4[ii][0] = fmaf(sv, vv.x, o4[ii][0]);
                o4[ii][1] = fmaf(sv, vv.y, o4[ii][1]);
                o4[ii][2] = fmaf(sv, vv.z, o4[ii][2]);
                o4[ii][3] = fmaf(sv, vv.w, o4[ii][3]);
            }
        }
#pragma unroll
        for (int ii = 0; ii < 4; ii++) {
            int qrow = qc * 64 + ty * 4 + ii;
            if (qrow < NKC) {
                int n = 1 + f * NKC + qrow;
                float4 ov = make_float4(o4[ii][0], o4[ii][1], o4[ii][2], o4[ii][3]);
                *(float4*)&g_att[((size_t)bh * NOUT + n) * 64 + tx * 4] = ov;
            }
        }
        __syncthreads();
    }
}

// ======================= launch =======================
extern "C" void kernel_launch(void* const* d_in, const int* in_sizes, int n_in,
                              void* d_out, int out_size)
{
    const float* x        = (const float*)d_in[0];
    const float* question = (const float*)d_in[1];
    const float* Wq       = (const float*)d_in[2];
    const float* Wkv      = (const float*)d_in[3];
    const float* Wproj    = (const float*)d_in[4];
    const float* bproj    = (const float*)d_in[5];
    float* out = (float*)d_out;

    cudaFuncSetAttribute(fine_attn, cudaFuncAttributeMaxDynamicSharedMemorySize, FINE_SMEM);
    cudaFuncSetAttribute(gemm_tc<0>, cudaFuncAttributeMaxDynamicSharedMemorySize, GEMM_SMEM);
    cudaFuncSetAttribute(gemm_tc<1>, cudaFuncAttributeMaxDynamicSharedMemorySize, GEMM_SMEM);
    cudaFuncSetAttribute(gemm_tc<2>, cudaFuncAttributeMaxDynamicSharedMemorySize, GEMM_SMEM);

    // weight transposes -> [N][K], tf32-rounded
    transposeW<<<dim3(768 / 32, 768 / 32), 256>>>(Wq, 0, 768, 768);
    transposeW<<<dim3(1536 / 32, 768 / 32), 256>>>(Wkv, 1, 768, 1536);
    transposeW<<<dim3(768 / 32, 768 / 32), 256>>>(Wproj, 2, 768, 768);

    // q projection: M=6304, N=768
    gemm_tc<0><<<dim3(768 / BN, (BB * NQ + BM - 1) / BM), 256, GEMM_SMEM>>>(
        question, nullptr, nullptr, BB * NQ);

    // kv projection: M=50176, N=1536
    gemm_tc<1><<<dim3(1536 / BN, (BB * NV) / BM), 256, GEMM_SMEM>>>(
        x, nullptr, nullptr, BB * NV);

    // attention
    cls_attn<<<BHN, 256>>>();
    fine_attn<<<BHN * FF, 256, FINE_SMEM>>>();

    // output projection: M=50208, N=768
    gemm_tc<2><<<dim3(768 / BN, (BB * NOUT + BM - 1) / BM), 256, GEMM_SMEM>>>(
        nullptr, bproj, out, BB * NOUT);
}

// round 4
// speedup vs baseline: 2.5842x; 1.4071x over previous
#include <cuda_runtime.h>
#include <cstdint>
#include <math.h>

// Problem constants
#define BB    32
#define NQ    197
#define NV    1568
#define DIMD  768
#define HH    12
#define FF    8
#define NKC   196
#define NOUT  1569
#define BHN   384
#define KDIM  768

// ---------------- scratch (device globals) ----------------
__device__ float g_q[(size_t)BHN * NQ * 64];
__device__ float g_k[(size_t)BHN * NV * 64];
__device__ float g_v[(size_t)BHN * NV * 64];
__device__ float g_att[(size_t)BHN * NOUT * 64];
__device__ float g_wqT[768 * 768];
__device__ float g_wkvT[1536 * 768];
__device__ float g_wpT[768 * 768];

// ======================= helpers =======================
__device__ __forceinline__ uint32_t smem_to_u32(const void* p) {
    uint32_t a;
    asm("{ .reg .u64 t; cvta.to.shared.u64 t, %1; cvt.u32.u64 %0, t; }" : "=r"(a) : "l"(p));
    return a;
}
__device__ __forceinline__ uint32_t to_tf32_rn(float x) {
    uint32_t r;
    asm("cvt.rn.tf32.f32 %0, %1;" : "=r"(r) : "f"(x));
    return r;
}
__device__ __forceinline__ float rnd_tf32(float x) { return __uint_as_float(to_tf32_rn(x)); }
__device__ __forceinline__ float4 f4_rnd(float4 v) {
    v.x = rnd_tf32(v.x); v.y = rnd_tf32(v.y); v.z = rnd_tf32(v.z); v.w = rnd_tf32(v.w);
    return v;
}
__device__ __forceinline__ void cp_async16(uint32_t smem_addr, const void* gptr, bool pred) {
    int sz = pred ? 16 : 0;
    asm volatile("cp.async.cg.shared.global [%0], [%1], 16, %2;"
                 :: "r"(smem_addr), "l"(gptr), "r"(sz));
}
#define CP_COMMIT() asm volatile("cp.async.commit_group;" ::: "memory")
#define CP_WAIT(n)  asm volatile("cp.async.wait_group %0;" :: "n"(n) : "memory")

__device__ __forceinline__ void mma_tf32(float* c, const uint32_t* a, const uint32_t* b) {
    asm volatile(
        "mma.sync.aligned.m16n8k8.row.col.f32.tf32.tf32.f32 "
        "{%0,%1,%2,%3}, {%4,%5,%6,%7}, {%8,%9}, {%0,%1,%2,%3};"
        : "+f"(c[0]), "+f"(c[1]), "+f"(c[2]), "+f"(c[3])
        : "r"(a[0]), "r"(a[1]), "r"(a[2]), "r"(a[3]), "r"(b[0]), "r"(b[1]));
}

// FMA-pipe exp (no MUFU): exp(x) = 2^(x*log2e), degree-5 poly + exponent splice.
__device__ __forceinline__ float fast_exp(float x) {
    x = fmaxf(x, -87.0f);
    float y = x * 1.4426950408889634f;
    float r = y + 12582912.0f;                       // 1.5*2^23: round-to-nearest
    int   n = __float_as_int(r) - 0x4B400000;
    float f = y - (r - 12582912.0f);                 // f in [-0.5, 0.5]
    float p = 1.3333558146e-3f;
    p = fmaf(p, f, 9.6181291076e-3f);
    p = fmaf(p, f, 5.5504108664e-2f);
    p = fmaf(p, f, 2.4022650696e-1f);
    p = fmaf(p, f, 6.9314718056e-1f);
    p = fmaf(p, f, 1.0f);
    return __int_as_float(__float_as_int(p) + (n << 23));
}

// ======================= weight transpose + tf32 round =======================
__global__ __launch_bounds__(256)
void transposeW(const float* __restrict__ src, int which, int K, int N)
{
    float* dst = (which == 0) ? g_wqT : (which == 1) ? g_wkvT : g_wpT;
    __shared__ float t[32][33];
    int bx = blockIdx.x * 32;
    int by = blockIdx.y * 32;
    int txl = threadIdx.x & 31;
    int tyl = threadIdx.x >> 5;
#pragma unroll
    for (int j = 0; j < 32; j += 8)
        t[tyl + j][txl] = src[(size_t)(by + tyl + j) * N + bx + txl];
    __syncthreads();
#pragma unroll
    for (int j = 0; j < 32; j += 8)
        dst[(size_t)(bx + tyl + j) * K + by + txl] = rnd_tf32(t[txl][tyl + j]);
}

// ======================= mma.sync tf32 GEMM (unchanged from R3) =======================
constexpr int BM = 128, BN = 128, BK = 32;
constexpr int SK = 36;
constexpr int A_BYTES = BM * SK * 4;
constexpr int STAGE_BYTES = 2 * A_BYTES;
constexpr int GEMM_SMEM = 2 * STAGE_BYTES;
constexpr int KT = KDIM / BK;

template<int MODE>
__global__ __launch_bounds__(256, 2)
void gemm_tc(const float* __restrict__ A, const float* __restrict__ bias,
             float* __restrict__ Cout, int M)
{
    extern __shared__ char sm[];
    const uint32_t sbase = smem_to_u32(sm);
    const int tid   = threadIdx.x;
    const int warp  = tid >> 5;
    const int lane  = tid & 31;
    const int group = lane >> 2;
    const int tig   = lane & 3;
    const int wm    = warp & 3;
    const int wn    = warp >> 2;
    const int row0  = blockIdx.y * BM;
    const int col0  = blockIdx.x * BN;

    const float* BT = (MODE == 0) ? g_wqT : (MODE == 1) ? g_wkvT : g_wpT;

    float acc[2][8][4];
#pragma unroll
    for (int mt = 0; mt < 2; mt++)
#pragma unroll
        for (int nt = 0; nt < 8; nt++)
#pragma unroll
            for (int c = 0; c < 4; c++) acc[mt][nt][c] = 0.f;

    const int lr = tid >> 3;
    const int lk4 = (tid & 7) << 2;

    auto load_stage = [&](int kt, int s) {
        const uint32_t aoff = sbase + s * STAGE_BYTES;
        const uint32_t boff = aoff + A_BYTES;
        const int k0 = kt * BK;
#pragma unroll
        for (int it = 0; it < 4; it++) {
            int r = lr + it * 32;
            int grow = row0 + r;
            bool ok = grow < M;
            int gr = ok ? grow : 0;
            const float* src;
            if (MODE == 2) {
                int b_ = gr / NOUT;
                int n_ = gr - b_ * NOUT;
                int kk = k0 + lk4;
                int h = kk >> 6, dd = kk & 63;
                src = &g_att[(((size_t)(b_ * HH + h) * NOUT + n_) << 6) + dd];
            } else {
                src = &A[(size_t)gr * KDIM + k0 + lk4];
            }
            cp_async16(aoff + (uint32_t)(r * SK + lk4) * 4, src, ok);
        }
#pragma unroll
        for (int it = 0; it < 4; it++) {
            int r = lr + it * 32;
            cp_async16(boff + (uint32_t)(r * SK + lk4) * 4,
                       &BT[(size_t)(col0 + r) * KDIM + k0 + lk4], true);
        }
        CP_COMMIT();
    };

    load_stage(0, 0);

    for (int kt = 0; kt < KT; kt++) {
        const int cur = kt & 1;
        if (kt + 1 < KT) {
            load_stage(kt + 1, (kt + 1) & 1);
            CP_WAIT(1);
        } else {
            CP_WAIT(0);
        }
        __syncthreads();

        const float* As = (const float*)(sm + cur * STAGE_BYTES);
        const float* Bs = (const float*)(sm + cur * STAGE_BYTES + A_BYTES);

#pragma unroll
        for (int ks = 0; ks < 4; ks++) {
            const int kc = ks * 8 + tig;
            uint32_t af[2][4];
#pragma unroll
            for (int mt = 0; mt < 2; mt++) {
                int r = wm * 32 + mt * 16 + group;
                af[mt][0] = to_tf32_rn(As[r * SK + kc]);
                af[mt][1] = to_tf32_rn(As[(r + 8) * SK + kc]);
                af[mt][2] = to_tf32_rn(As[r * SK + kc + 4]);
                af[mt][3] = to_tf32_rn(As[(r + 8) * SK + kc + 4]);
            }
#pragma unroll
            for (int nt = 0; nt < 8; nt++) {
                int n = wn * 64 + nt * 8 + group;
                uint32_t bf[2];
                bf[0] = __float_as_uint(Bs[n * SK + kc]);
                bf[1] = __float_as_uint(Bs[n * SK + kc + 4]);
                mma_tf32(acc[0][nt], af[0], bf);
                mma_tf32(acc[1][nt], af[1], bf);
            }
        }
        __syncthreads();
    }

#pragma unroll
    for (int mt = 0; mt < 2; mt++) {
#pragma unroll
        for (int half = 0; half < 2; half++) {
            int row = row0 + wm * 32 + mt * 16 + group + half * 8;
            if (row >= M) continue;
            int b_, n_;
            if (MODE == 0) { b_ = row / NQ;   n_ = row - b_ * NQ; }
            else if (MODE == 1) { b_ = row / NV; n_ = row - b_ * NV; }
            else { b_ = 0; n_ = 0; }
#pragma unroll
            for (int nt = 0; nt < 8; nt++) {
                int col = col0 + wn * 64 + nt * 8 + tig * 2;
                float v0 = acc[mt][nt][half * 2 + 0];
                float v1 = acc[mt][nt][half * 2 + 1];
                if (MODE == 0) {
                    int h = col >> 6, dd = col & 63;
                    float2 w = make_float2(v0 * 0.125f, v1 * 0.125f);
                    *(float2*)&g_q[(((size_t)(b_ * HH + h) * NQ + n_) << 6) + dd] = w;
                } else if (MODE == 1) {
                    float2 w = make_float2(v0, v1);
                    if (col < DIMD) {
                        int h = col >> 6, dd = col & 63;
                        *(float2*)&g_k[(((size_t)(b_ * HH + h) * NV + n_) << 6) + dd] = w;
                    } else {
                        int c2 = col - DIMD;
                        int h = c2 >> 6, dd = c2 & 63;
                        *(float2*)&g_v[(((size_t)(b_ * HH + h) * NV + n_) << 6) + dd] = w;
                    }
                } else {
                    float2 w = make_float2(v0 + bias[col], v1 + bias[col + 1]);
                    *(float2*)&Cout[(size_t)row * DIMD + col] = w;
                }
            }
        }
    }
}

// ======================= cls-token attention =======================
__global__ __launch_bounds__(256)
void cls_attn()
{
    __shared__ float qsh[64];
    __shared__ float ssh[NV];
    __shared__ float red[40];
    __shared__ float osh[4][64];

    const int bh   = blockIdx.x;
    const int tid  = threadIdx.x;
    const int lane = tid & 31;
    const int warp = tid >> 5;

    if (tid < 64) qsh[tid] = g_q[((size_t)bh * NQ) * 64 + tid];
    __syncthreads();

    for (int j = warp; j < NV; j += 8) {
        const float* kr = &g_k[((size_t)bh * NV + j) * 64];
        float p = qsh[lane] * kr[lane] + qsh[lane + 32] * kr[lane + 32];
#pragma unroll
        for (int o = 16; o > 0; o >>= 1) p += __shfl_xor_sync(0xffffffffu, p, o);
        if (lane == 0) ssh[j] = p;
    }
    __syncthreads();

    float m = -1e30f;
    for (int j = tid; j < NV; j += 256) m = fmaxf(m, ssh[j]);
#pragma unroll
    for (int o = 16; o > 0; o >>= 1) m = fmaxf(m, __shfl_xor_sync(0xffffffffu, m, o));
    if (lane == 0) red[warp] = m;
    __syncthreads();
    if (tid == 0) {
        float mm = red[0];
        for (int w = 1; w < 8; w++) mm = fmaxf(mm, red[w]);
        red[32] = mm;
    }
    __syncthreads();
    m = red[32];

    float s = 0.f;
    for (int j = tid; j < NV; j += 256) {
        float e = fast_exp(ssh[j] - m);
        ssh[j] = e;
        s += e;
    }
#pragma unroll
    for (int o = 16; o > 0; o >>= 1) s += __shfl_xor_sync(0xffffffffu, s, o);
    if (lane == 0) red[8 + warp] = s;
    __syncthreads();
    if (tid == 0) {
        float ss = 0.f;
        for (int w = 0; w < 8; w++) ss += red[8 + w];
        red[33] = 1.f / ss;
    }
    __syncthreads();
    const float inv = red[33];

    const int g = tid >> 6, dd = tid & 63;
    float o = 0.f;
    for (int j = g; j < NV; j += 4)
        o = fmaf(ssh[j], g_v[((size_t)bh * NV + j) * 64 + dd], o);
    osh[g][dd] = o;
    __syncthreads();
    if (tid < 64) {
        float r = (osh[0][tid] + osh[1][tid] + osh[2][tid] + osh[3][tid]) * inv;
        g_att[((size_t)bh * NOUT) * 64 + tid] = r;
    }
}

// ======================= fine attention — tensor cores =======================
// Per block (bh, f): S = Q(196x64) K^T, softmax, O = P V. Queries in 4 chunks of 64.
// smem strides tuned for conflict-free m16n8k8 fragment access.
constexpr int QW = 68;                   // Q  [64][68]
constexpr int KW = 68;                   // K  [224][68] (rows 196..223 zero)
constexpr int VW = 204;                  // Vt [64][204]  (cols 196..203 zero)
constexpr int SW = 228;                  // S  [64][228]
constexpr int Q_OFF = 0;
constexpr int K_OFF = Q_OFF + 64 * QW;           // 4352
constexpr int V_OFF = K_OFF + 224 * KW;          // 19584
constexpr int S_OFF = V_OFF + 64 * VW;           // 32640
constexpr int I_OFF = S_OFF + 64 * SW;           // 47232
constexpr int FINE_SMEM = (I_OFF + 64) * 4;      // 189184 bytes

__global__ __launch_bounds__(256, 1)
void fine_attn()
{
    extern __shared__ float smf[];
    float* Qs = smf + Q_OFF;
    float* Ks = smf + K_OFF;
    float* Vt = smf + V_OFF;
    float* Ss = smf + S_OFF;
    float* Iv = smf + I_OFF;

    const int bh    = blockIdx.x >> 3;
    const int f     = blockIdx.x & 7;
    const int tid   = threadIdx.x;
    const int warp  = tid >> 5;
    const int lane  = tid & 31;
    const int group = lane >> 2;
    const int tig   = lane & 3;

    // ---- load K (196x64, tf32-rounded), zero pad rows 196..223
    const float* kg = &g_k[((size_t)bh * NV + (size_t)f * NKC) * 64];
    const float* vg = &g_v[((size_t)bh * NV + (size_t)f * NKC) * 64];
    for (int idx = tid; idx < NKC * 16; idx += 256) {
        int j = idx >> 4, d4 = (idx & 15) << 2;
        *(float4*)&Ks[j * KW + d4] = f4_rnd(*(const float4*)&kg[j * 64 + d4]);
    }
    for (int idx = tid; idx < 28 * 17; idx += 256) {
        int r = 196 + idx / 17, c4 = (idx % 17) * 4;
        *(float4*)&Ks[r * KW + c4] = make_float4(0.f, 0.f, 0.f, 0.f);
    }
    // ---- stage V natural into S region (stride 68), rounded
    for (int idx = tid; idx < NKC * 16; idx += 256) {
        int j = idx >> 4, d4 = (idx & 15) << 2;
        *(float4*)&Ss[j * 68 + d4] = f4_rnd(*(const float4*)&vg[j * 64 + d4]);
    }
    __syncthreads();
    // ---- transpose Vn (S region) -> Vt; zero pad cols
    {
        int d = tid & 63;
        for (int j = tid >> 6; j < NKC; j += 4)
            Vt[d * VW + j] = Ss[j * 68 + d];
    }
    for (int idx = tid; idx < 64 * 8; idx += 256) {
        int d = idx >> 3, c = 196 + (idx & 7);
        Vt[d * VW + c] = 0.f;
    }
    // NOTE: sync below (after Q load) orders transpose-reads before S-phase writes.

    for (int qc = 0; qc < 4; qc++) {
        const int rows = (qc == 3) ? (NKC - 192) : 64;

        // ---- load Q chunk (rounded, zero-padded rows)
        for (int idx = tid; idx < 64 * 16; idx += 256) {
            int i = idx >> 4, d4 = (idx & 15) << 2;
            float4 v = make_float4(0.f, 0.f, 0.f, 0.f);
            if (i < rows)
                v = f4_rnd(*(const float4*)&g_q[((size_t)bh * NQ + 1 + qc * 64 + i) * 64 + d4]);
            *(float4*)&Qs[i * QW + d4] = v;
        }
        __syncthreads();

        // ---- S = Q @ K^T : warps 2M x 4N, warp tile 32 x 56
        {
            const int wm = warp & 1, wn = warp >> 1;
            float acc[2][7][4];
#pragma unroll
            for (int mt = 0; mt < 2; mt++)
#pragma unroll
                for (int nt = 0; nt < 7; nt++)
#pragma unroll
                    for (int c = 0; c < 4; c++) acc[mt][nt][c] = 0.f;

#pragma unroll
            for (int ks = 0; ks < 8; ks++) {
                const int kc = ks * 8 + tig;
                uint32_t af[2][4];
#pragma unroll
                for (int mt = 0; mt < 2; mt++) {
                    int r = wm * 32 + mt * 16 + group;
                    af[mt][0] = __float_as_uint(Qs[r * QW + kc]);
                    af[mt][1] = __float_as_uint(Qs[(r + 8) * QW + kc]);
                    af[mt][2] = __float_as_uint(Qs[r * QW + kc + 4]);
                    af[mt][3] = __float_as_uint(Qs[(r + 8) * QW + kc + 4]);
                }
#pragma unroll
                for (int nt = 0; nt < 7; nt++) {
                    int n = wn * 56 + nt * 8 + group;
                    uint32_t bf[2];
                    bf[0] = __float_as_uint(Ks[n * KW + kc]);
                    bf[1] = __float_as_uint(Ks[n * KW + kc + 4]);
                    mma_tf32(acc[0][nt], af[0], bf);
                    mma_tf32(acc[1][nt], af[1], bf);
                }
            }
            // store S fragments
#pragma unroll
            for (int mt = 0; mt < 2; mt++) {
                int r = wm * 32 + mt * 16 + group;
#pragma unroll
                for (int nt = 0; nt < 7; nt++) {
                    int n = wn * 56 + nt * 8 + tig * 2;
                    *(float2*)&Ss[r * SW + n]       = make_float2(acc[mt][nt][0], acc[mt][nt][1]);
                    *(float2*)&Ss[(r + 8) * SW + n] = make_float2(acc[mt][nt][2], acc[mt][nt][3]);
                }
            }
        }
        __syncthreads();

        // ---- softmax over valid cols (j<196); normalization deferred to PV epilogue
        for (int r = warp * 8; r < warp * 8 + 8; r++) {
            float* srow = &Ss[r * SW];
            float mx = -1e30f;
            for (int j = lane; j < NKC; j += 32) mx = fmaxf(mx, srow[j]);
#pragma unroll
            for (int o = 16; o > 0; o >>= 1) mx = fmaxf(mx, __shfl_xor_sync(0xffffffffu, mx, o));
            float sum = 0.f;
            for (int j = lane; j < NKC; j += 32) {
                float e = fast_exp(srow[j] - mx);
                srow[j] = rnd_tf32(e);
                sum += e;
            }
#pragma unroll
            for (int o = 16; o > 0; o >>= 1) sum += __shfl_xor_sync(0xffffffffu, sum, o);
            if (lane == 0) Iv[r] = 1.f / sum;
        }
        __syncthreads();

        // ---- O = P @ V : warps 2M x 4N, warp tile 32 x 16; k over 200 (pad cols are 0)
        {
            const int wm = warp & 1, wn = warp >> 1;
            float acc[2][2][4];
#pragma unroll
            for (int mt = 0; mt < 2; mt++)
#pragma unroll
                for (int nt = 0; nt < 2; nt++)
#pragma unroll
                    for (int c = 0; c < 4; c++) acc[mt][nt][c] = 0.f;

            for (int ks = 0; ks < 25; ks++) {
                const int kc = ks * 8 + tig;
                uint32_t af[2][4];
#pragma unroll
                for (int mt = 0; mt < 2; mt++) {
                    int r = wm * 32 + mt * 16 + group;
                    af[mt][0] = __float_as_uint(Ss[r * SW + kc]);
                    af[mt][1] = __float_as_uint(Ss[(r + 8) * SW + kc]);
                    af[mt][2] = __float_as_uint(Ss[r * SW + kc + 4]);
                    af[mt][3] = __float_as_uint(Ss[(r + 8) * SW + kc + 4]);
                }
#pragma unroll
                for (int nt = 0; nt < 2; nt++) {
                    int n = wn * 16 + nt * 8 + group;
                    uint32_t bf[2];
                    bf[0] = __float_as_uint(Vt[n * VW + kc]);
                    bf[1] = __float_as_uint(Vt[n * VW + kc + 4]);
                    mma_tf32(acc[0][nt], af[0], bf);
                    mma_tf32(acc[1][nt], af[1], bf);
                }
            }
            // epilogue: scale by 1/sum, write g_att
#pragma unroll
            for (int mt = 0; mt < 2; mt++) {
#pragma unroll
                for (int half = 0; half < 2; half++) {
                    int rl = wm * 32 + mt * 16 + group + half * 8;
                    int qrow = qc * 64 + rl;
                    if (qrow >= NKC) continue;
                    float iv = Iv[rl];
                    size_t base = ((size_t)bh * NOUT + 1 + (size_t)f * NKC + qrow) * 64;
#pragma unroll
                    for (int nt = 0; nt < 2; nt++) {
                        int col = (warp >> 1) * 16 + nt * 8 + tig * 2;
                        float2 w = make_float2(acc[mt][nt][half * 2] * iv,
                                               acc[mt][nt][half * 2 + 1] * iv);
                        *(float2*)&g_att[base + col] = w;
                    }
                }
            }
        }
        __syncthreads();
    }
}

// ======================= launch =======================
extern "C" void kernel_launch(void* const* d_in, const int* in_sizes, int n_in,
                              void* d_out, int out_size)
{
    const float* x        = (const float*)d_in[0];
    const float* question = (const float*)d_in[1];
    const float* Wq       = (const float*)d_in[2];
    const float* Wkv      = (const float*)d_in[3];
    const float* Wproj    = (const float*)d_in[4];
    const float* bproj    = (const float*)d_in[5];
    float* out = (float*)d_out;

    cudaFuncSetAttribute(fine_attn, cudaFuncAttributeMaxDynamicSharedMemorySize, FINE_SMEM);
    cudaFuncSetAttribute(gemm_tc<0>, cudaFuncAttributeMaxDynamicSharedMemorySize, GEMM_SMEM);
    cudaFuncSetAttribute(gemm_tc<1>, cudaFuncAttributeMaxDynamicSharedMemorySize, GEMM_SMEM);
    cudaFuncSetAttribute(gemm_tc<2>, cudaFuncAttributeMaxDynamicSharedMemorySize, GEMM_SMEM);

    transposeW<<<dim3(768 / 32, 768 / 32), 256>>>(Wq, 0, 768, 768);
    transposeW<<<dim3(1536 / 32, 768 / 32), 256>>>(Wkv, 1, 768, 1536);
    transposeW<<<dim3(768 / 32, 768 / 32), 256>>>(Wproj, 2, 768, 768);

    gemm_tc<0><<<dim3(768 / BN, (BB * NQ + BM - 1) / BM), 256, GEMM_SMEM>>>(
        question, nullptr, nullptr, BB * NQ);

    gemm_tc<1><<<dim3(1536 / BN, (BB * NV) / BM), 256, GEMM_SMEM>>>(
        x, nullptr, nullptr, BB * NV);

    cls_attn<<<BHN, 256>>>();
    fine_attn<<<BHN * FF, 256, FINE_SMEM>>>();

    gemm_tc<2><<<dim3(768 / BN, (BB * NOUT + BM - 1) / BM), 256, GEMM_SMEM>>>(
        nullptr, bproj, out, BB * NOUT);
}